// round 3
// baseline (speedup 1.0000x reference)
#include <cuda_runtime.h>
#include <math.h>

// Problem dims
#define Tt   257
#define Bb   16
#define Hh   1024
#define G4   4096
#define Ee   512
#define Ss   512
#define Vv   1024
#define MT   (Tt*Bb)        // 4112
#define SOS_TOK 1
#define EOS_TOK 2

typedef unsigned long long ull;

// ---------------- device scratch (no cudaMalloc allowed) ----------------
#define WROWS 1028          // 1024 + 4 pad rows for prefetch over-read
__device__ float d_WT[5][WROWS*G4];      // transposed weights [k][g]: 0=hh0 1=ih1 2=hh1 3=ih2 4=hh2
__device__ float d_xW0[(long long)MT*G4];// [t*16+b][4096]
__device__ float d_hT[3][Hh*Bb];         // [k][b] transposed hidden state per layer
__device__ float d_cS[3][Bb*Hh];         // [b][k] cell state per layer
__device__ float d_bias[3][G4];
__device__ float d_part[40][Bb*G4];      // K-split partials [slot][b][col]
__device__ float d_hs[(long long)MT*Hh];     // [b*257+t][1024]
__device__ float d_scores[(long long)Bb*Tt*Ss];
__device__ float d_ctx[(long long)MT*Hh];
__device__ float d_hidden[(long long)MT*Hh];
__device__ float d_logits[(long long)MT*Vv];

// ---------------- f32x2 helpers (Blackwell FFMA2) ----------------
__device__ __forceinline__ void ffma2(ull& d, ull a, ull b) {
    asm("fma.rn.f32x2 %0, %1, %2, %0;" : "+l"(d) : "l"(a), "l"(b));
}
__device__ __forceinline__ ull splat2(float x) {
    ull r; asm("mov.b64 %0, {%1, %1};" : "=l"(r) : "f"(x)); return r;
}
__device__ __forceinline__ float2 upk(ull v) {
    float2 r; asm("mov.b64 {%0, %1}, %2;" : "=f"(r.x), "=f"(r.y) : "l"(v)); return r;
}
__device__ __forceinline__ ull pack2(float a, float b) {
    ull r; asm("mov.b64 %0, {%1, %2};" : "=l"(r) : "f"(a), "f"(b)); return r;
}

// ---------------- init: zero states, fold biases ----------------
__global__ void k_init(const float* __restrict__ bih0, const float* __restrict__ bhh0,
                       const float* __restrict__ bih1, const float* __restrict__ bhh1,
                       const float* __restrict__ bih2, const float* __restrict__ bhh2) {
    int i = blockIdx.x * 256 + threadIdx.x;
    if (i < 3 * Hh * Bb) {
        ((float*)d_hT)[i] = 0.f;
        ((float*)d_cS)[i] = 0.f;
    }
    if (i < G4) {
        d_bias[0][i] = bih0[i] + bhh0[i];
        d_bias[1][i] = bih1[i] + bhh1[i];
        d_bias[2][i] = bih2[i] + bhh2[i];
    }
}

// ---------------- transpose W [4096][1024] -> WT [k][4096] ----------------
__global__ void k_transpose(const float* __restrict__ src, int which) {
    __shared__ float t[32][33];
    float* dst = d_WT[which];
    int k0 = blockIdx.x * 32, g0 = blockIdx.y * 32;
    int x = threadIdx.x, y = threadIdx.y;  // block (32,8)
#pragma unroll
    for (int j = 0; j < 32; j += 8)
        t[y + j][x] = src[(long long)(g0 + y + j) * 1024 + k0 + x];
    __syncthreads();
#pragma unroll
    for (int j = 0; j < 32; j += 8)
        dst[(long long)(k0 + y + j) * G4 + g0 + x] = t[x][y + j];
}

// ---------------- generic tiled GEMM: C[M][N] = epi(A @ B^T(+)) ----------------
// 64(M) x 128(N) block tile, BK=16, 128 threads, per-thread 8x8 via f32x2 (M-pairs).
// AMODE: 0 plain A[row][k] (lda), 1 embedding gather (row=(t,b)=m), 2 concat(hs,ctx)
// BMODE: 0 B[n][k] (NT), 1 B[k][n] (NN)
// EPI:   0 none, 1 +bias, 2 tanh(.+bias)
template<int AMODE, int BMODE, int EPI>
__global__ __launch_bounds__(128)
void k_gemm(const float* __restrict__ A, int lda, long long Az,
            const float* __restrict__ Bm, int ldb, long long Bz,
            float* __restrict__ C, int ldc, long long Cz,
            const float* __restrict__ bias,
            int M, int N, int K,
            const int* __restrict__ toks,
            const float* __restrict__ A2)
{
    __shared__ float As[16][72];
    __shared__ float Bs[16][136];
    int z = blockIdx.z;
    const float* Ab = A + Az * z;
    const float* Bv = Bm + Bz * z;
    float* Cb = C + Cz * z;
    int m0 = blockIdx.x * 64, n0 = blockIdx.y * 128;
    int tid = threadIdx.x;
    int tm = tid >> 4, tn = tid & 15;

    ull acc[4][8];
#pragma unroll
    for (int p = 0; p < 4; p++)
#pragma unroll
        for (int c = 0; c < 8; c++) acc[p][c] = 0ull;

    for (int kt = 0; kt < K; kt += 16) {
        // stage A (64 x 16), transposed into As[k][m]
#pragma unroll
        for (int i = 0; i < 2; i++) {
            int id = tid * 2 + i;
            int r = id >> 2, kq = (id & 3) * 4;
            int row = m0 + r; if (row >= M) row = M - 1;
            float4 v;
            if (AMODE == 0) {
                v = *(const float4*)(Ab + (long long)row * lda + kt + kq);
            } else if (AMODE == 1) {
                int t = row >> 4, b = row & 15;
                int tok = (t == 0) ? SOS_TOK : toks[b * 256 + t - 1];
                v = *(const float4*)(Ab + (long long)tok * Ee + kt + kq);
            } else {
                int kk = kt + kq;
                const float* src = (kk < 1024) ? (A + (long long)row * 1024 + kk)
                                               : (A2 + (long long)row * 1024 + kk - 1024);
                v = *(const float4*)src;
            }
            As[kq + 0][r] = v.x; As[kq + 1][r] = v.y; As[kq + 2][r] = v.z; As[kq + 3][r] = v.w;
        }
        // stage B (128 x 16) into Bs[k][n]
        if (BMODE == 0) {
#pragma unroll
            for (int i = 0; i < 4; i++) {
                int id = tid * 4 + i;
                int n = id >> 2, kq = (id & 3) * 4;
                float4 v = *(const float4*)(Bv + (long long)(n0 + n) * ldb + kt + kq);
                Bs[kq + 0][n] = v.x; Bs[kq + 1][n] = v.y; Bs[kq + 2][n] = v.z; Bs[kq + 3][n] = v.w;
            }
        } else {
#pragma unroll
            for (int i = 0; i < 4; i++) {
                int id = tid * 4 + i;
                int kk = id >> 5, nq = (id & 31) * 4;
                float4 v = *(const float4*)(Bv + (long long)(kt + kk) * ldb + n0 + nq);
                *(float4*)&Bs[kk][nq] = v;
            }
        }
        __syncthreads();
#pragma unroll
        for (int k = 0; k < 16; k++) {
            float4 a0 = *(const float4*)&As[k][tm * 8];
            float4 a1 = *(const float4*)&As[k][tm * 8 + 4];
            ull pa[4];
            pa[0] = pack2(a0.x, a0.y); pa[1] = pack2(a0.z, a0.w);
            pa[2] = pack2(a1.x, a1.y); pa[3] = pack2(a1.z, a1.w);
            float4 b0 = *(const float4*)&Bs[k][tn * 8];
            float4 b1 = *(const float4*)&Bs[k][tn * 8 + 4];
            ull wb[8];
            wb[0] = splat2(b0.x); wb[1] = splat2(b0.y); wb[2] = splat2(b0.z); wb[3] = splat2(b0.w);
            wb[4] = splat2(b1.x); wb[5] = splat2(b1.y); wb[6] = splat2(b1.z); wb[7] = splat2(b1.w);
#pragma unroll
            for (int p = 0; p < 4; p++)
#pragma unroll
                for (int c = 0; c < 8; c++)
                    ffma2(acc[p][c], pa[p], wb[c]);
        }
        __syncthreads();
    }
    // epilogue
    int ncol = n0 + tn * 8;
#pragma unroll
    for (int r = 0; r < 8; r++) {
        int row = m0 + tm * 8 + r;
        if (row < M) {
            float o[8];
#pragma unroll
            for (int c = 0; c < 8; c++) {
                float2 u = upk(acc[r >> 1][c]);
                o[c] = (r & 1) ? u.y : u.x;
            }
            if (EPI >= 1) {
#pragma unroll
                for (int c = 0; c < 8; c++) o[c] += bias[ncol + c];
            }
            if (EPI == 2) {
#pragma unroll
                for (int c = 0; c < 8; c++) o[c] = tanhf(o[c]);
            }
            float4 v0 = make_float4(o[0], o[1], o[2], o[3]);
            float4 v1 = make_float4(o[4], o[5], o[6], o[7]);
            *(float4*)(Cb + (long long)row * ldc + ncol) = v0;
            *(float4*)(Cb + (long long)row * ldc + ncol + 4) = v1;
        }
    }
}

// ---------------- recurrence: gates partials ----------------
// 320 blocks/wave: L0: 8colTiles x 8kChunks; L1: ih 64 + hh 64; L2: 128.
// Block: 128 thr, tile 16(batch) x 512(cols), kChunk=128. Per thread: 16b x 4cols.
__global__ __launch_bounds__(128)
void k_gates(int w) {
    int bi = blockIdx.x;
    int layer, term, ct, kIdx, slot;
    if (bi < 64)       { layer = 0; term = 0; ct = bi >> 3; kIdx = bi & 7; slot = kIdx; }
    else if (bi < 192) { int r = bi - 64;  layer = 1; term = r >> 6; r &= 63; ct = r >> 3; kIdx = r & 7; slot = 8  + term * 8 + kIdx; }
    else               { int r = bi - 192; layer = 2; term = r >> 6; r &= 63; ct = r >> 3; kIdx = r & 7; slot = 24 + term * 8 + kIdx; }
    int t = w - layer;
    if (t < 0 || t >= Tt) return;

    const float* W; const float* hsrc;
    if (layer == 0)      { W = d_WT[0];                     hsrc = d_hT[0]; }
    else if (layer == 1) { W = term ? d_WT[2] : d_WT[1];    hsrc = term ? d_hT[1] : d_hT[0]; }
    else                 { W = term ? d_WT[4] : d_WT[3];    hsrc = term ? d_hT[2] : d_hT[1]; }

    int k0 = kIdx * 128;
    int tid = threadIdx.x, warp = tid >> 5, lane = tid & 31;
    int c0 = ct * 512 + warp * 128 + lane * 4;

    __shared__ float hs_sm[128 * 16];  // [k][b], 8KB
    {
        const float4* src = (const float4*)(hsrc + k0 * 16);
        float4* dst = (float4*)hs_sm;
#pragma unroll
        for (int i = tid; i < 512; i += 128) dst[i] = src[i];
    }
    __syncthreads();

    ull acc[8][4];
#pragma unroll
    for (int p = 0; p < 8; p++)
#pragma unroll
        for (int c = 0; c < 4; c++) acc[p][c] = 0ull;

    const float4* Wp = (const float4*)(W + (long long)k0 * G4 + c0);  // stride 1024 float4 per k
    float4 wbuf[4];
#pragma unroll
    for (int j = 0; j < 4; j++) wbuf[j] = Wp[j * 1024];

    const ull* hU = (const ull*)hs_sm;
#pragma unroll 1
    for (int k = 0; k < 128; k += 4) {
#pragma unroll
        for (int j = 0; j < 4; j++) {
            float4 wv = wbuf[j];
            wbuf[j] = Wp[(k + 4 + j) * 1024];   // prefetch (padded rows make tail safe)
            ull w0 = splat2(wv.x), w1 = splat2(wv.y), w2 = splat2(wv.z), w3 = splat2(wv.w);
            const ull* hp = hU + (k + j) * 8;
            ulonglong2 q0 = *(const ulonglong2*)(hp + 0);
            ulonglong2 q1 = *(const ulonglong2*)(hp + 2);
            ulonglong2 q2 = *(const ulonglong2*)(hp + 4);
            ulonglong2 q3 = *(const ulonglong2*)(hp + 6);
            ull pr[8] = { q0.x, q0.y, q1.x, q1.y, q2.x, q2.y, q3.x, q3.y };
#pragma unroll
            for (int p = 0; p < 8; p++) {
                ffma2(acc[p][0], pr[p], w0);
                ffma2(acc[p][1], pr[p], w1);
                ffma2(acc[p][2], pr[p], w2);
                ffma2(acc[p][3], pr[p], w3);
            }
        }
    }
    // write partials: [slot][b][col], float4 per b -> fully coalesced per warp
    float* dst = d_part[slot];
#pragma unroll
    for (int b = 0; b < 16; b++) {
        int pp = b >> 1;
        float2 u0 = upk(acc[pp][0]), u1 = upk(acc[pp][1]), u2 = upk(acc[pp][2]), u3 = upk(acc[pp][3]);
        float4 v = (b & 1) ? make_float4(u0.y, u1.y, u2.y, u3.y)
                           : make_float4(u0.x, u1.x, u2.x, u3.x);
        *(float4*)(dst + b * G4 + c0) = v;
    }
}

// ---------------- recurrence: cell (reduce partials, activations, state update) ----------------
__global__ void k_cell(int w) {
    int bx = blockIdx.x;
    int layer = bx >> 6, chunk = bx & 63;
    int t = w - layer;
    if (t < 0 || t >= Tt) return;
    int cid = chunk * 256 + threadIdx.x;
    int b = cid >> 10, k = cid & 1023;

    int s0, ns;
    if (layer == 0)      { s0 = 0;  ns = 8; }
    else if (layer == 1) { s0 = 8;  ns = 16; }
    else                 { s0 = 24; ns = 16; }

    float gv[4];
#pragma unroll
    for (int gi = 0; gi < 4; gi++) {
        int col = k + (gi << 10);
        float v = d_bias[layer][col];
        if (layer == 0) v += d_xW0[((long long)(t * 16 + b)) * G4 + col];
        for (int s = 0; s < ns; s++) v += d_part[s0 + s][b * G4 + col];
        gv[gi] = v;
    }
    float i_ = 1.f / (1.f + __expf(-gv[0]));
    float f_ = 1.f / (1.f + __expf(-gv[1]));
    float g_ = tanhf(gv[2]);
    float o_ = 1.f / (1.f + __expf(-gv[3]));
    float c = f_ * d_cS[layer][b * 1024 + k] + i_ * g_;
    d_cS[layer][b * 1024 + k] = c;
    float h = o_ * tanhf(c);
    d_hT[layer][k * 16 + b] = h;
    if (layer == 2) d_hs[((long long)b * Tt + t) * 1024 + k] = h;
}

// ---------------- softmax over attention scores (in place) ----------------
__global__ void k_softmax(float* __restrict__ sc) {
    long long row = blockIdx.x;
    float* p = sc + row * Ss;
    int tid = threadIdx.x;  // 128
    __shared__ float red[4], red2[4];
    float mx = -1e30f;
    float vals[4];
#pragma unroll
    for (int j = 0; j < 4; j++) { vals[j] = p[tid + j * 128]; mx = fmaxf(mx, vals[j]); }
#pragma unroll
    for (int o = 16; o; o >>= 1) mx = fmaxf(mx, __shfl_xor_sync(0xffffffffu, mx, o));
    if ((tid & 31) == 0) red[tid >> 5] = mx;
    __syncthreads();
    mx = fmaxf(fmaxf(red[0], red[1]), fmaxf(red[2], red[3]));
    float s = 0.f;
#pragma unroll
    for (int j = 0; j < 4; j++) { vals[j] = __expf(vals[j] - mx); s += vals[j]; }
#pragma unroll
    for (int o = 16; o; o >>= 1) s += __shfl_xor_sync(0xffffffffu, s, o);
    if ((tid & 31) == 0) red2[tid >> 5] = s;
    __syncthreads();
    s = red2[0] + red2[1] + red2[2] + red2[3];
    float inv = 1.f / s;
#pragma unroll
    for (int j = 0; j < 4; j++) p[tid + j * 128] = vals[j] * inv;
}

// ---------------- loss ----------------
__global__ void k_zero(float* out) { if (threadIdx.x == 0) out[0] = 0.f; }

__global__ void k_loss(const int* __restrict__ toks, float* __restrict__ out) {
    int m = blockIdx.x;             // b*257 + t
    int b = m / Tt, t = m % Tt;
    const float* p = d_logits + (long long)m * Vv;
    int tid = threadIdx.x;          // 256
    __shared__ float red[8];
    float mx = -1e30f;
    float v[4];
#pragma unroll
    for (int j = 0; j < 4; j++) { v[j] = p[tid + j * 256]; mx = fmaxf(mx, v[j]); }
#pragma unroll
    for (int o = 16; o; o >>= 1) mx = fmaxf(mx, __shfl_xor_sync(0xffffffffu, mx, o));
    if ((tid & 31) == 0) red[tid >> 5] = mx;
    __syncthreads();
    mx = red[0];
#pragma unroll
    for (int i = 1; i < 8; i++) mx = fmaxf(mx, red[i]);
    __syncthreads();
    float s = 0.f;
#pragma unroll
    for (int j = 0; j < 4; j++) s += __expf(v[j] - mx);
#pragma unroll
    for (int o = 16; o; o >>= 1) s += __shfl_xor_sync(0xffffffffu, s, o);
    if ((tid & 31) == 0) red[tid >> 5] = s;
    __syncthreads();
    if (tid == 0) {
        float tot = 0.f;
#pragma unroll
        for (int i = 0; i < 8; i++) tot += red[i];
        int tgt = (t < 256) ? toks[b * 256 + t] : EOS_TOK;
        float nll = logf(tot) + mx - p[tgt];
        atomicAdd(out, nll * (1.f / (float)MT));
    }
}

// ---------------- host launch ----------------
extern "C" void kernel_launch(void* const* d_in, const int* in_sizes, int n_in,
                              void* d_out, int out_size) {
    const int*   tokens = (const int*)d_in[0];
    const float* enc    = (const float*)d_in[1];
    const float* emb    = (const float*)d_in[2];
    const float* Wih0   = (const float*)d_in[3];
    const float* Whh0   = (const float*)d_in[4];
    const float* bih0   = (const float*)d_in[5];
    const float* bhh0   = (const float*)d_in[6];
    const float* Wih1   = (const float*)d_in[7];
    const float* Whh1   = (const float*)d_in[8];
    const float* bih1   = (const float*)d_in[9];
    const float* bhh1   = (const float*)d_in[10];
    const float* Wih2   = (const float*)d_in[11];
    const float* Whh2   = (const float*)d_in[12];
    const float* bih2   = (const float*)d_in[13];
    const float* bhh2   = (const float*)d_in[14];
    const float* W1     = (const float*)d_in[15];
    const float* b1     = (const float*)d_in[16];
    const float* W2     = (const float*)d_in[17];
    const float* b2     = (const float*)d_in[18];
    float* out = (float*)d_out;

    float *p_xW0, *p_hs, *p_scores, *p_ctx, *p_hidden, *p_logits;
    cudaGetSymbolAddress((void**)&p_xW0,    d_xW0);
    cudaGetSymbolAddress((void**)&p_hs,     d_hs);
    cudaGetSymbolAddress((void**)&p_scores, d_scores);
    cudaGetSymbolAddress((void**)&p_ctx,    d_ctx);
    cudaGetSymbolAddress((void**)&p_hidden, d_hidden);
    cudaGetSymbolAddress((void**)&p_logits, d_logits);

    // init states + biases
    k_init<<<192, 256>>>(bih0, bhh0, bih1, bhh1, bih2, bhh2);

    // transpose recurrent weight matrices
    dim3 tb(32, 8), tg(32, 128);
    k_transpose<<<tg, tb>>>(Whh0, 0);
    k_transpose<<<tg, tb>>>(Wih1, 1);
    k_transpose<<<tg, tb>>>(Whh1, 2);
    k_transpose<<<tg, tb>>>(Wih2, 3);
    k_transpose<<<tg, tb>>>(Whh2, 4);

    // xW0 = emb(dec_in) @ W_ih0[:, :512]^T   (M=4112 rows as m=t*16+b)
    k_gemm<1, 0, 0><<<dim3(65, 32, 1), 128>>>(emb, Ee, 0,
                                              Wih0, Ee + 1024, 0,
                                              p_xW0, G4, 0,
                                              nullptr, MT, G4, Ee, tokens, nullptr);

    // recurrence: 259 waves
    for (int w = 0; w < Tt + 2; w++) {
        k_gates<<<320, 128>>>(w);
        k_cell<<<192, 256>>>(w);
    }

    // attention scores: per b, hs[257,1024] @ enc_b[512,1024]^T
    k_gemm<0, 0, 0><<<dim3(5, 4, 16), 128>>>(p_hs, Hh, (long long)Tt * Hh,
                                             enc, Hh, (long long)Ss * Hh,
                                             p_scores, Ss, (long long)Tt * Ss,
                                             nullptr, Tt, Ss, Hh, nullptr, nullptr);
    // softmax
    k_softmax<<<MT, 128>>>(p_scores);
    // ctx: attn[257,512] @ enc_b[512,1024]  (NN)
    k_gemm<0, 1, 0><<<dim3(5, 8, 16), 128>>>(p_scores, Ss, (long long)Tt * Ss,
                                             enc, Hh, (long long)Ss * Hh,
                                             p_ctx, Hh, (long long)Tt * Hh,
                                             nullptr, Tt, Hh, Ss, nullptr, nullptr);
    // hidden = tanh(concat(hs,ctx) @ W1^T + b1)
    k_gemm<2, 0, 2><<<dim3(65, 8, 1), 128>>>(p_hs, 2048, 0,
                                             W1, 2048, 0,
                                             p_hidden, Hh, 0,
                                             b1, MT, Hh, 2048, nullptr, p_ctx);
    // logits = hidden @ W2^T + b2
    k_gemm<0, 0, 1><<<dim3(65, 8, 1), 128>>>(p_hidden, Hh, 0,
                                             W2, Hh, 0,
                                             p_logits, Vv, 0,
                                             b2, MT, Vv, Hh, nullptr, nullptr);
    // loss
    k_zero<<<1, 32>>>(out);
    k_loss<<<MT, 256>>>(tokens, out);
}